// round 6
// baseline (speedup 1.0000x reference)
#include <cuda_runtime.h>
#include <cuda_bf16.h>
#include <math.h>
#include <stdint.h>

#define NPEDS_MAX 8192
#define H 256
#define E 64
#define G4 1024   // 4*H
#define KTOT 320  // E + H
#define SEQ 30
#define KT_TILES 10  // KTOT/32

// ---- device-global scratch (no allocations allowed) ----
// h double-buffered: GEMM step s reads buf (s&1), writes buf ((s+1)&1).
__device__ __align__(16) __nv_bfloat16 g_h[2][NPEDS_MAX * H];
__device__ __align__(16) float g_hf[NPEDS_MAX * H];          // fp32 h for tail LN2
__device__ float g_c[NPEDS_MAX * H];
__device__ __align__(16) __nv_bfloat16 g_x[NPEDS_MAX * E];
__device__ __align__(16) __nv_bfloat16 g_Wn[G4 * KTOT];  // [n'][k], n' = ch*4+gate
__device__ __align__(16) float g_bias4[G4];              // [ch][gate] interleaved

__device__ __forceinline__ float sigm(float v) { return 1.f / (1.f + expf(-v)); }

// ---------------------------------------------------------------------------
// Init kernels (run every graph replay -> deterministic state reset)
// ---------------------------------------------------------------------------
__global__ void prep_weights(const float* __restrict__ W_ih, const float* __restrict__ W_hh,
                             const float* __restrict__ b_ih, const float* __restrict__ b_hh) {
  int idx = blockIdx.x * blockDim.x + threadIdx.x;
  if (idx < G4 * KTOT) {
    int np = idx / KTOT, k = idx - np * KTOT;
    int n = (np & 3) * 256 + (np >> 2);       // gate-major original row
    float w = (k < E) ? W_ih[n * E + k] : W_hh[n * H + (k - E)];
    g_Wn[idx] = __float2bfloat16(w);
  }
  if (idx < G4) {
    int gate = idx & 3, ch = idx >> 2;
    int n = gate * 256 + ch;
    g_bias4[idx] = b_ih[n] + b_hh[n];
  }
}

__global__ void init_state(const float* __restrict__ h0, const float* __restrict__ c0, int n) {
  int idx = blockIdx.x * blockDim.x + threadIdx.x;
  if (idx < n) {
    g_h[0][idx] = __float2bfloat16(h0[idx]);
    g_c[idx] = c0[idx];
  }
}

// embed(p) = leaky_relu( LN_2(p) @ emb_W^T + emb_b )
__global__ void embed_init(const float* __restrict__ lpr,
                           const float* __restrict__ ln1_g, const float* __restrict__ ln1_b,
                           const float* __restrict__ emb_W, const float* __restrict__ emb_b,
                           int npeds) {
  int idx = blockIdx.x * blockDim.x + threadIdx.x;
  if (idx >= npeds * E) return;
  int ped = idx / E, j = idx - ped * E;
  float a = lpr[ped * 2 + 0], b = lpr[ped * 2 + 1];
  float d = 0.5f * (a - b);
  float inv = rsqrtf(d * d + 1e-5f);
  float na =  d * inv * ln1_g[0] + ln1_b[0];
  float nb = -d * inv * ln1_g[1] + ln1_b[1];
  float y = na * emb_W[j * 2 + 0] + nb * emb_W[j * 2 + 1] + emb_b[j];
  g_x[idx] = __float2bfloat16((y > 0.f) ? y : 0.01f * y);
}

// ---------------------------------------------------------------------------
// Fused GEMM + LSTM cell update (race-free via h double-buffering).
//   gates[M,1024] = [x|h_rd][M,320] @ Wn'^T  (gate-interleaved columns),
//   epilogue: per-cell LSTM -> writes h_wr (bf16), g_hf (fp32), g_c (fp32).
// BM=128, BN=128, BK=32, 8 warps (2m x 4n), mma.m16n8k16.bf16, cp.async x2.
// ---------------------------------------------------------------------------
__global__ __launch_bounds__(256, 2) void gates_gemm(int rdbuf, int npeds) {
  __shared__ __align__(16) uint32_t As[2][128][20];  // [m][k-pairs], 80B rows
  __shared__ __align__(16) uint32_t Bs[2][128][20];  // [n'][k-pairs]

  const __nv_bfloat16* __restrict__ h_rd = g_h[rdbuf];
  __nv_bfloat16* __restrict__ h_wr = g_h[rdbuf ^ 1];

  const int bm = blockIdx.y * 128;
  const int bn = blockIdx.x * 128;
  const int t = threadIdx.x;
  const int warp = t >> 5;
  const int lane = t & 31;
  const int wm = (warp >> 2) * 64;
  const int wn = (warp & 3) * 32;
  const int gr = lane >> 2;   // 0..7
  const int lc = lane & 3;    // 0..3

  float acc[4][4][4];
#pragma unroll
  for (int i = 0; i < 4; ++i)
#pragma unroll
    for (int j = 0; j < 4; ++j)
#pragma unroll
      for (int q = 0; q < 4; ++q) acc[i][j][q] = 0.f;

  const int mm0 = t >> 2;          // 0..63
  const int c4 = t & 3;            // 16B chunk

  auto load_tile = [&](int kt, int buf) {
    const int k0 = kt * 32;
    const __nv_bfloat16* srcA;
    int ldk, koff;
    if (k0 < E) { srcA = g_x; ldk = E; koff = k0; }
    else        { srcA = h_rd; ldk = H; koff = k0 - E; }
#pragma unroll
    for (int r = 0; r < 2; ++r) {
      const int mm = mm0 + r * 64;
      const void* gA = srcA + (size_t)(bm + mm) * ldk + koff + c4 * 8;
      uint32_t dA = (uint32_t)__cvta_generic_to_shared(&As[buf][mm][c4 * 4]);
      asm volatile("cp.async.cg.shared.global [%0], [%1], 16;\n" :: "r"(dA), "l"(gA));
      const void* gB = g_Wn + (size_t)(bn + mm) * KTOT + k0 + c4 * 8;
      uint32_t dB = (uint32_t)__cvta_generic_to_shared(&Bs[buf][mm][c4 * 4]);
      asm volatile("cp.async.cg.shared.global [%0], [%1], 16;\n" :: "r"(dB), "l"(gB));
    }
    asm volatile("cp.async.commit_group;\n");
  };

  load_tile(0, 0);

  for (int kt = 0; kt < KT_TILES; ++kt) {
    asm volatile("cp.async.wait_group 0;\n");
    __syncthreads();
    if (kt + 1 < KT_TILES) load_tile(kt + 1, (kt + 1) & 1);
    const int buf = kt & 1;

#pragma unroll
    for (int ks = 0; ks < 2; ++ks) {
      const int kb = ks * 8;
      uint32_t a[4][4], b[4][2];
#pragma unroll
      for (int mt = 0; mt < 4; ++mt) {
        const int ar = wm + mt * 16 + gr;
        a[mt][0] = As[buf][ar][kb + lc];
        a[mt][1] = As[buf][ar + 8][kb + lc];
        a[mt][2] = As[buf][ar][kb + lc + 4];
        a[mt][3] = As[buf][ar + 8][kb + lc + 4];
      }
#pragma unroll
      for (int nt = 0; nt < 4; ++nt) {
        const int br = wn + nt * 8 + gr;
        b[nt][0] = Bs[buf][br][kb + lc];
        b[nt][1] = Bs[buf][br][kb + lc + 4];
      }
#pragma unroll
      for (int mt = 0; mt < 4; ++mt)
#pragma unroll
        for (int nt = 0; nt < 4; ++nt) {
          asm volatile(
            "mma.sync.aligned.m16n8k16.row.col.f32.bf16.bf16.f32 "
            "{%0,%1,%2,%3}, {%4,%5,%6,%7}, {%8,%9}, {%0,%1,%2,%3};"
            : "+f"(acc[mt][nt][0]), "+f"(acc[mt][nt][1]),
              "+f"(acc[mt][nt][2]), "+f"(acc[mt][nt][3])
            : "r"(a[mt][0]), "r"(a[mt][1]), "r"(a[mt][2]), "r"(a[mt][3]),
              "r"(b[nt][0]), "r"(b[nt][1]));
        }
    }
  }

  // ---- fused LSTM epilogue ----
  // Columns gate-interleaved: local col pairs (lc even -> i,f | lc odd -> g,o).
  // shfl_xor(1) pairs the lanes; even lane computes row gr, odd lane row gr+8.
  const bool odd = (lc & 1);
#pragma unroll
  for (int mt = 0; mt < 4; ++mt) {
    const int row = bm + wm + mt * 16 + gr + (odd ? 8 : 0);
#pragma unroll
    for (int nt = 0; nt < 4; ++nt) {
      const float q0 = acc[mt][nt][0], q1 = acc[mt][nt][1];
      const float q2 = acc[mt][nt][2], q3 = acc[mt][nt][3];
      const float v0 = __shfl_xor_sync(0xffffffffu, q0, 1);
      const float v1 = __shfl_xor_sync(0xffffffffu, q1, 1);
      const float v2 = __shfl_xor_sync(0xffffffffu, q2, 1);
      const float v3 = __shfl_xor_sync(0xffffffffu, q3, 1);
      const float gi = odd ? v2 : q0;
      const float gf = odd ? v3 : q1;
      const float gg = odd ? q2 : v0;
      const float go = odd ? q3 : v1;
      const int ch = ((bn + wn + nt * 8) >> 2) + (lc >> 1);
      const float4 bi = *(const float4*)&g_bias4[ch * 4];
      const float cv = g_c[(size_t)row * H + ch];
      const float cn = sigm(gf + bi.y) * cv + sigm(gi + bi.x) * tanhf(gg + bi.z);
      const float hv = sigm(go + bi.w) * tanhf(cn);
      g_c[(size_t)row * H + ch] = cn;
      h_wr[(size_t)row * H + ch] = __float2bfloat16(hv);
      g_hf[(size_t)row * H + ch] = hv;
    }
  }
}

// ---------------------------------------------------------------------------
// Per-step tail: LN2 + pos projection (rel out) + embed(rel) -> next x.
// One warp per ped; lane owns 8 contiguous channels. Reads fp32 h (g_hf).
// ---------------------------------------------------------------------------
__global__ __launch_bounds__(256) void ln_proj_embed(
    const float* __restrict__ ln2_g, const float* __restrict__ ln2_b,
    const float* __restrict__ pos_W, const float* __restrict__ pos_b,
    const float* __restrict__ emb_W, const float* __restrict__ emb_b,
    const float* __restrict__ ln1_g, const float* __restrict__ ln1_b,
    float* __restrict__ rel_out, int npeds) {
  const int warp = threadIdx.x >> 5;
  const int lane = threadIdx.x & 31;
  const int ped = blockIdx.x * 8 + warp;
  if (ped >= npeds) return;

  const float* hp = g_hf + (size_t)ped * H + lane * 8;
  float hn[8];
  {
    float4 u0 = *(const float4*)hp;
    float4 u1 = *(const float4*)(hp + 4);
    hn[0] = u0.x; hn[1] = u0.y; hn[2] = u0.z; hn[3] = u0.w;
    hn[4] = u1.x; hn[5] = u1.y; hn[6] = u1.z; hn[7] = u1.w;
  }
  float s = 0.f, ss = 0.f;
#pragma unroll
  for (int q = 0; q < 8; ++q) { s += hn[q]; ss += hn[q] * hn[q]; }
#pragma unroll
  for (int o = 16; o > 0; o >>= 1) {
    s += __shfl_xor_sync(0xffffffffu, s, o);
    ss += __shfl_xor_sync(0xffffffffu, ss, o);
  }
  const float mu = s * (1.f / 256.f);
  const float var = ss * (1.f / 256.f) - mu * mu;
  const float rstd = rsqrtf(var + 1e-5f);

  float d0 = 0.f, d1 = 0.f;
  const int ch0 = lane * 8;
#pragma unroll
  for (int q = 0; q < 8; ++q) {
    const float nh = (hn[q] - mu) * rstd * ln2_g[ch0 + q] + ln2_b[ch0 + q];
    d0 += nh * pos_W[ch0 + q];
    d1 += nh * pos_W[256 + ch0 + q];
  }
#pragma unroll
  for (int o = 16; o > 0; o >>= 1) {
    d0 += __shfl_xor_sync(0xffffffffu, d0, o);
    d1 += __shfl_xor_sync(0xffffffffu, d1, o);
  }
  const float r0 = sigm(d0 + pos_b[0]);
  const float r1 = sigm(d1 + pos_b[1]);
  if (lane == 0) {
    rel_out[(size_t)ped * 2 + 0] = r0;
    rel_out[(size_t)ped * 2 + 1] = r1;
  }

  // embed(rel) -> next x  (LN over 2 elems)
  const float d = 0.5f * (r0 - r1);
  const float inv = rsqrtf(d * d + 1e-5f);
  const float na =  d * inv * ln1_g[0] + ln1_b[0];
  const float nb = -d * inv * ln1_g[1] + ln1_b[1];
  __nv_bfloat16* xp = g_x + (size_t)ped * E;
#pragma unroll
  for (int q = 0; q < 2; ++q) {
    const int j = lane * 2 + q;
    const float y = na * emb_W[j * 2 + 0] + nb * emb_W[j * 2 + 1] + emb_b[j];
    xp[j] = __float2bfloat16((y > 0.f) ? y : 0.01f * y);
  }
}

// ---------------------------------------------------------------------------
extern "C" void kernel_launch(void* const* d_in, const int* in_sizes, int n_in,
                              void* d_out, int out_size) {
  const float* last_pos_rel = (const float*)d_in[1];
  const float* h0   = (const float*)d_in[2];
  const float* c0   = (const float*)d_in[3];
  const float* W_ih = (const float*)d_in[4];
  const float* W_hh = (const float*)d_in[5];
  const float* b_ih = (const float*)d_in[6];
  const float* b_hh = (const float*)d_in[7];
  const float* emb_W = (const float*)d_in[8];
  const float* emb_b = (const float*)d_in[9];
  const float* ln1_g = (const float*)d_in[10];
  const float* ln1_b = (const float*)d_in[11];
  const float* pos_W = (const float*)d_in[12];
  const float* pos_b = (const float*)d_in[13];
  const float* ln2_g = (const float*)d_in[14];
  const float* ln2_b = (const float*)d_in[15];
  float* out = (float*)d_out;

  const int npeds = in_sizes[0] / 2;  // 8192

  prep_weights<<<(G4 * KTOT + 255) / 256, 256>>>(W_ih, W_hh, b_ih, b_hh);
  init_state<<<(npeds * H + 255) / 256, 256>>>(h0, c0, npeds * H);
  embed_init<<<(npeds * E + 255) / 256, 256>>>(last_pos_rel, ln1_g, ln1_b, emb_W, emb_b, npeds);

  dim3 ggrid(G4 / 128, npeds / 128);
  for (int s = 0; s < SEQ; ++s) {
    gates_gemm<<<ggrid, 256>>>(s & 1, npeds);
    ln_proj_embed<<<npeds / 8, 256>>>(ln2_g, ln2_b, pos_W, pos_b, emb_W, emb_b,
                                      ln1_g, ln1_b, out + (size_t)s * npeds * 2, npeds);
  }
}

// round 7
// speedup vs baseline: 2.4407x; 2.4407x over previous
#include <cuda_runtime.h>
#include <cuda_bf16.h>
#include <math.h>
#include <stdint.h>

#define NPEDS_MAX 8192
#define H 256
#define E 64
#define G4 1024   // 4*H
#define KTOT 320  // E + H
#define SEQ 30
#define KT_TILES 10  // KTOT/32

// ---- device-global scratch (no allocations allowed) ----
// h double-buffered: GEMM step s reads buf (s&1), writes buf ((s+1)&1).
__device__ __align__(16) __nv_bfloat16 g_h[2][NPEDS_MAX * H];
__device__ __align__(16) float g_hf[NPEDS_MAX * H];          // fp32 h for tail LN2
__device__ float g_c[NPEDS_MAX * H];
__device__ __align__(16) __nv_bfloat16 g_x[NPEDS_MAX * E];
__device__ __align__(16) __nv_bfloat16 g_Wn[G4 * KTOT];  // [n'][k], n' = ch*4+gate
__device__ __align__(16) float g_bias4[G4];              // [ch][gate] interleaved

__device__ __forceinline__ float sigm(float v) { return 1.f / (1.f + expf(-v)); }

// ---------------------------------------------------------------------------
// Init kernels (run every graph replay -> deterministic state reset)
// ---------------------------------------------------------------------------
__global__ void prep_weights(const float* __restrict__ W_ih, const float* __restrict__ W_hh,
                             const float* __restrict__ b_ih, const float* __restrict__ b_hh) {
  int idx = blockIdx.x * blockDim.x + threadIdx.x;
  if (idx < G4 * KTOT) {
    int np = idx / KTOT, k = idx - np * KTOT;
    int n = (np & 3) * 256 + (np >> 2);       // gate-major original row
    float w = (k < E) ? W_ih[n * E + k] : W_hh[n * H + (k - E)];
    g_Wn[idx] = __float2bfloat16(w);
  }
  if (idx < G4) {
    int gate = idx & 3, ch = idx >> 2;
    int n = gate * 256 + ch;
    g_bias4[idx] = b_ih[n] + b_hh[n];
  }
}

__global__ void init_state(const float* __restrict__ h0, const float* __restrict__ c0, int n) {
  int idx = blockIdx.x * blockDim.x + threadIdx.x;
  if (idx < n) {
    g_h[0][idx] = __float2bfloat16(h0[idx]);
    g_c[idx] = c0[idx];
  }
}

// embed(p) = leaky_relu( LN_2(p) @ emb_W^T + emb_b )
__global__ void embed_init(const float* __restrict__ lpr,
                           const float* __restrict__ ln1_g, const float* __restrict__ ln1_b,
                           const float* __restrict__ emb_W, const float* __restrict__ emb_b,
                           int npeds) {
  int idx = blockIdx.x * blockDim.x + threadIdx.x;
  if (idx >= npeds * E) return;
  int ped = idx / E, j = idx - ped * E;
  float a = lpr[ped * 2 + 0], b = lpr[ped * 2 + 1];
  float d = 0.5f * (a - b);
  float inv = rsqrtf(d * d + 1e-5f);
  float na =  d * inv * ln1_g[0] + ln1_b[0];
  float nb = -d * inv * ln1_g[1] + ln1_b[1];
  float y = na * emb_W[j * 2 + 0] + nb * emb_W[j * 2 + 1] + emb_b[j];
  g_x[idx] = __float2bfloat16((y > 0.f) ? y : 0.01f * y);
}

// ---------------------------------------------------------------------------
// Fused GEMM + LSTM cell update (race-free; smem-staged coalesced epilogue).
// BM=128, BN=128(=32 ch), BK=32, 8 warps (2m x 4n), mma.m16n8k16.bf16.
// ---------------------------------------------------------------------------
union SmemU {
  struct { uint32_t As[2][128][20]; uint32_t Bs[2][128][20]; } p;  // 40 KB
  struct { float c[128][33]; float h[128][33]; } e;                // 33 KB
};

__global__ __launch_bounds__(256, 2) void gates_gemm(int rdbuf, int npeds) {
  __shared__ SmemU sm;

  const __nv_bfloat16* __restrict__ h_rd = g_h[rdbuf];
  __nv_bfloat16* __restrict__ h_wr = g_h[rdbuf ^ 1];

  const int bm = blockIdx.y * 128;
  const int bn = blockIdx.x * 128;
  const int t = threadIdx.x;
  const int warp = t >> 5;
  const int lane = t & 31;
  const int wm = (warp >> 2) * 64;
  const int wn = (warp & 3) * 32;
  const int gr = lane >> 2;   // 0..7
  const int lc = lane & 3;    // 0..3

  float acc[4][4][4];
#pragma unroll
  for (int i = 0; i < 4; ++i)
#pragma unroll
    for (int j = 0; j < 4; ++j)
#pragma unroll
      for (int q = 0; q < 4; ++q) acc[i][j][q] = 0.f;

  const int mm0 = t >> 2;          // 0..63
  const int c4 = t & 3;            // 16B chunk

  auto load_tile = [&](int kt, int buf) {
    const int k0 = kt * 32;
    const __nv_bfloat16* srcA;
    int ldk, koff;
    if (k0 < E) { srcA = g_x; ldk = E; koff = k0; }
    else        { srcA = h_rd; ldk = H; koff = k0 - E; }
#pragma unroll
    for (int r = 0; r < 2; ++r) {
      const int mm = mm0 + r * 64;
      const void* gA = srcA + (size_t)(bm + mm) * ldk + koff + c4 * 8;
      uint32_t dA = (uint32_t)__cvta_generic_to_shared(&sm.p.As[buf][mm][c4 * 4]);
      asm volatile("cp.async.cg.shared.global [%0], [%1], 16;\n" :: "r"(dA), "l"(gA));
      const void* gB = g_Wn + (size_t)(bn + mm) * KTOT + k0 + c4 * 8;
      uint32_t dB = (uint32_t)__cvta_generic_to_shared(&sm.p.Bs[buf][mm][c4 * 4]);
      asm volatile("cp.async.cg.shared.global [%0], [%1], 16;\n" :: "r"(dB), "l"(gB));
    }
    asm volatile("cp.async.commit_group;\n");
  };

  load_tile(0, 0);

  for (int kt = 0; kt < KT_TILES; ++kt) {
    asm volatile("cp.async.wait_group 0;\n");
    __syncthreads();
    if (kt + 1 < KT_TILES) load_tile(kt + 1, (kt + 1) & 1);
    const int buf = kt & 1;

#pragma unroll
    for (int ks = 0; ks < 2; ++ks) {
      const int kb = ks * 8;
      uint32_t a[4][4], b[4][2];
#pragma unroll
      for (int mt = 0; mt < 4; ++mt) {
        const int ar = wm + mt * 16 + gr;
        a[mt][0] = sm.p.As[buf][ar][kb + lc];
        a[mt][1] = sm.p.As[buf][ar + 8][kb + lc];
        a[mt][2] = sm.p.As[buf][ar][kb + lc + 4];
        a[mt][3] = sm.p.As[buf][ar + 8][kb + lc + 4];
      }
#pragma unroll
      for (int nt = 0; nt < 4; ++nt) {
        const int br = wn + nt * 8 + gr;
        b[nt][0] = sm.p.Bs[buf][br][kb + lc];
        b[nt][1] = sm.p.Bs[buf][br][kb + lc + 4];
      }
#pragma unroll
      for (int mt = 0; mt < 4; ++mt)
#pragma unroll
        for (int nt = 0; nt < 4; ++nt) {
          asm volatile(
            "mma.sync.aligned.m16n8k16.row.col.f32.bf16.bf16.f32 "
            "{%0,%1,%2,%3}, {%4,%5,%6,%7}, {%8,%9}, {%0,%1,%2,%3};"
            : "+f"(acc[mt][nt][0]), "+f"(acc[mt][nt][1]),
              "+f"(acc[mt][nt][2]), "+f"(acc[mt][nt][3])
            : "r"(a[mt][0]), "r"(a[mt][1]), "r"(a[mt][2]), "r"(a[mt][3]),
              "r"(b[nt][0]), "r"(b[nt][1]));
        }
    }
  }

  // ================= fused LSTM epilogue (smem-staged, coalesced) ===========
  __syncthreads();                       // done reading As/Bs; smem reused
  const int chbase = bn >> 2;            // 32 channels per CTA column tile

  // Phase A: coalesced load of c tile into smem (warp = 128B per row)
#pragma unroll
  for (int r = 0; r < 16; ++r) {
    const int row = r * 8 + warp;
    sm.e.c[row][lane] = g_c[(size_t)(bm + row) * H + chbase + lane];
  }
  __syncthreads();

  // Phase B: per-thread gate math on smem tile.
  // Columns gate-interleaved: lc even -> (i,f), lc odd -> (g,o);
  // shfl_xor(1) pairs lanes; even lane does row gr, odd lane row gr+8.
  const bool odd = (lc & 1);
#pragma unroll
  for (int mt = 0; mt < 4; ++mt) {
    const int rowL = wm + mt * 16 + gr + (odd ? 8 : 0);
#pragma unroll
    for (int nt = 0; nt < 4; ++nt) {
      const float q0 = acc[mt][nt][0], q1 = acc[mt][nt][1];
      const float q2 = acc[mt][nt][2], q3 = acc[mt][nt][3];
      const float v0 = __shfl_xor_sync(0xffffffffu, q0, 1);
      const float v1 = __shfl_xor_sync(0xffffffffu, q1, 1);
      const float v2 = __shfl_xor_sync(0xffffffffu, q2, 1);
      const float v3 = __shfl_xor_sync(0xffffffffu, q3, 1);
      const float gi = odd ? v2 : q0;
      const float gf = odd ? v3 : q1;
      const float gg = odd ? q2 : v0;
      const float go = odd ? q3 : v1;
      const int chL = ((wn + nt * 8) >> 2) + (lc >> 1);
      const float4 bi = *(const float4*)&g_bias4[(chbase + chL) * 4];
      const float cv = sm.e.c[rowL][chL];
      const float cn = sigm(gf + bi.y) * cv + sigm(gi + bi.x) * tanhf(gg + bi.z);
      const float hv = sigm(go + bi.w) * tanhf(cn);
      sm.e.c[rowL][chL] = cn;
      sm.e.h[rowL][chL] = hv;
    }
  }
  __syncthreads();

  // Phase C: coalesced writeback
#pragma unroll
  for (int r = 0; r < 16; ++r) {
    const int row = r * 8 + warp;
    const size_t off = (size_t)(bm + row) * H + chbase + lane;
    g_c[off] = sm.e.c[row][lane];
    g_hf[off] = sm.e.h[row][lane];
  }
#pragma unroll
  for (int r = 0; r < 8; ++r) {
    const int row = r * 16 + warp * 2 + (lane >> 4);
    const int ch2 = lane & 15;
    __nv_bfloat162 v = __floats2bfloat162_rn(sm.e.h[row][ch2 * 2],
                                             sm.e.h[row][ch2 * 2 + 1]);
    *(__nv_bfloat162*)(h_wr + (size_t)(bm + row) * H + chbase + ch2 * 2) = v;
  }
}

// ---------------------------------------------------------------------------
// Per-step tail: LN2 + pos projection (rel out) + embed(rel) -> next x.
// One warp per ped; lane owns 8 contiguous channels. Reads fp32 h (g_hf).
// ---------------------------------------------------------------------------
__global__ __launch_bounds__(256) void ln_proj_embed(
    const float* __restrict__ ln2_g, const float* __restrict__ ln2_b,
    const float* __restrict__ pos_W, const float* __restrict__ pos_b,
    const float* __restrict__ emb_W, const float* __restrict__ emb_b,
    const float* __restrict__ ln1_g, const float* __restrict__ ln1_b,
    float* __restrict__ rel_out, int npeds) {
  const int warp = threadIdx.x >> 5;
  const int lane = threadIdx.x & 31;
  const int ped = blockIdx.x * 8 + warp;
  if (ped >= npeds) return;

  const float* hp = g_hf + (size_t)ped * H + lane * 8;
  float hn[8];
  {
    float4 u0 = *(const float4*)hp;
    float4 u1 = *(const float4*)(hp + 4);
    hn[0] = u0.x; hn[1] = u0.y; hn[2] = u0.z; hn[3] = u0.w;
    hn[4] = u1.x; hn[5] = u1.y; hn[6] = u1.z; hn[7] = u1.w;
  }
  float s = 0.f, ss = 0.f;
#pragma unroll
  for (int q = 0; q < 8; ++q) { s += hn[q]; ss += hn[q] * hn[q]; }
#pragma unroll
  for (int o = 16; o > 0; o >>= 1) {
    s += __shfl_xor_sync(0xffffffffu, s, o);
    ss += __shfl_xor_sync(0xffffffffu, ss, o);
  }
  const float mu = s * (1.f / 256.f);
  const float var = ss * (1.f / 256.f) - mu * mu;
  const float rstd = rsqrtf(var + 1e-5f);

  float d0 = 0.f, d1 = 0.f;
  const int ch0 = lane * 8;
#pragma unroll
  for (int q = 0; q < 8; ++q) {
    const float nh = (hn[q] - mu) * rstd * ln2_g[ch0 + q] + ln2_b[ch0 + q];
    d0 += nh * pos_W[ch0 + q];
    d1 += nh * pos_W[256 + ch0 + q];
  }
#pragma unroll
  for (int o = 16; o > 0; o >>= 1) {
    d0 += __shfl_xor_sync(0xffffffffu, d0, o);
    d1 += __shfl_xor_sync(0xffffffffu, d1, o);
  }
  const float r0 = sigm(d0 + pos_b[0]);
  const float r1 = sigm(d1 + pos_b[1]);
  if (lane == 0) {
    rel_out[(size_t)ped * 2 + 0] = r0;
    rel_out[(size_t)ped * 2 + 1] = r1;
  }

  // embed(rel) -> next x  (LN over 2 elems)
  const float d = 0.5f * (r0 - r1);
  const float inv = rsqrtf(d * d + 1e-5f);
  const float na =  d * inv * ln1_g[0] + ln1_b[0];
  const float nb = -d * inv * ln1_g[1] + ln1_b[1];
  __nv_bfloat16* xp = g_x + (size_t)ped * E;
#pragma unroll
  for (int q = 0; q < 2; ++q) {
    const int j = lane * 2 + q;
    const float y = na * emb_W[j * 2 + 0] + nb * emb_W[j * 2 + 1] + emb_b[j];
    xp[j] = __float2bfloat16((y > 0.f) ? y : 0.01f * y);
  }
}

// ---------------------------------------------------------------------------
extern "C" void kernel_launch(void* const* d_in, const int* in_sizes, int n_in,
                              void* d_out, int out_size) {
  const float* last_pos_rel = (const float*)d_in[1];
  const float* h0   = (const float*)d_in[2];
  const float* c0   = (const float*)d_in[3];
  const float* W_ih = (const float*)d_in[4];
  const float* W_hh = (const float*)d_in[5];
  const float* b_ih = (const float*)d_in[6];
  const float* b_hh = (const float*)d_in[7];
  const float* emb_W = (const float*)d_in[8];
  const float* emb_b = (const float*)d_in[9];
  const float* ln1_g = (const float*)d_in[10];
  const float* ln1_b = (const float*)d_in[11];
  const float* pos_W = (const float*)d_in[12];
  const float* pos_b = (const float*)d_in[13];
  const float* ln2_g = (const float*)d_in[14];
  const float* ln2_b = (const float*)d_in[15];
  float* out = (float*)d_out;

  const int npeds = in_sizes[0] / 2;  // 8192

  prep_weights<<<(G4 * KTOT + 255) / 256, 256>>>(W_ih, W_hh, b_ih, b_hh);
  init_state<<<(npeds * H + 255) / 256, 256>>>(h0, c0, npeds * H);
  embed_init<<<(npeds * E + 255) / 256, 256>>>(last_pos_rel, ln1_g, ln1_b, emb_W, emb_b, npeds);

  dim3 ggrid(G4 / 128, npeds / 128);
  for (int s = 0; s < SEQ; ++s) {
    gates_gemm<<<ggrid, 256>>>(s & 1, npeds);
    ln_proj_embed<<<npeds / 8, 256>>>(ln2_g, ln2_b, pos_W, pos_b, emb_W, emb_b,
                                      ln1_g, ln1_b, out + (size_t)s * npeds * 2, npeds);
  }
}

// round 8
// speedup vs baseline: 2.4780x; 1.0153x over previous
#include <cuda_runtime.h>
#include <cuda_bf16.h>
#include <math.h>
#include <stdint.h>

#define NPEDS_MAX 8192
#define H 256
#define E 64
#define G4 1024   // 4*H
#define KTOT 320  // E + H
#define SEQ 30
#define NT 5      // k-tiles of 64

// ---- device-global scratch (no allocations allowed) ----
__device__ __align__(16) __nv_bfloat16 g_h[NPEDS_MAX * H];
__device__ float g_c[NPEDS_MAX * H];
__device__ __align__(16) __nv_bfloat16 g_x[NPEDS_MAX * E];
__device__ float g_gates[NPEDS_MAX * G4];
__device__ __align__(16) __nv_bfloat16 g_Wn[G4 * KTOT];  // [n][k] bf16, gate-major n
__device__ float g_bias[G4];

__device__ __forceinline__ float sigm(float v) { return 1.f / (1.f + __expf(-v)); }
__device__ __forceinline__ float tanh_fast(float v) {
  return 2.f / (1.f + __expf(-2.f * v)) - 1.f;
}

// ---------------------------------------------------------------------------
// Init kernels (run every graph replay -> deterministic state reset)
// ---------------------------------------------------------------------------
__global__ void prep_weights(const float* __restrict__ W_ih, const float* __restrict__ W_hh,
                             const float* __restrict__ b_ih, const float* __restrict__ b_hh) {
  int idx = blockIdx.x * blockDim.x + threadIdx.x;
  if (idx < G4 * KTOT) {
    int n = idx / KTOT, k = idx - n * KTOT;
    float w = (k < E) ? W_ih[n * E + k] : W_hh[n * H + (k - E)];
    g_Wn[idx] = __float2bfloat16(w);
  }
  if (idx < G4) g_bias[idx] = b_ih[idx] + b_hh[idx];
}

__global__ void init_state(const float* __restrict__ h0, const float* __restrict__ c0, int n) {
  int idx = blockIdx.x * blockDim.x + threadIdx.x;
  if (idx < n) { g_h[idx] = __float2bfloat16(h0[idx]); g_c[idx] = c0[idx]; }
}

// embed(p) = leaky_relu( LN_2(p) @ emb_W^T + emb_b )
__global__ void embed_init(const float* __restrict__ lpr,
                           const float* __restrict__ ln1_g, const float* __restrict__ ln1_b,
                           const float* __restrict__ emb_W, const float* __restrict__ emb_b,
                           int npeds) {
  int idx = blockIdx.x * blockDim.x + threadIdx.x;
  if (idx >= npeds * E) return;
  int ped = idx / E, j = idx - ped * E;
  float a = lpr[ped * 2 + 0], b = lpr[ped * 2 + 1];
  float d = 0.5f * (a - b);
  float inv = rsqrtf(d * d + 1e-5f);
  float na =  d * inv * ln1_g[0] + ln1_b[0];
  float nb = -d * inv * ln1_g[1] + ln1_b[1];
  float y = na * emb_W[j * 2 + 0] + nb * emb_W[j * 2 + 1] + emb_b[j];
  g_x[idx] = __float2bfloat16((y > 0.f) ? y : 0.01f * y);
}

// ---------------------------------------------------------------------------
// Per-step GEMM (bf16 MMA, BK=64, 2-stage cp.async, dynamic smem 72KB):
//   g_gates[M,1024] = [x|h][M,320] @ Wn^T  (Wn stored [n][k])
// BM=128, BN=128, 8 warps (2m x 4n), warp tile 64x32, mma.m16n8k16.
// smem rows padded to 36 uint32 (144B): 4-bank shift/row -> conflict-free frags.
// ---------------------------------------------------------------------------
#define ROWU 36                       // uint32 per smem row (32 data + 4 pad)
#define TILEU (128 * ROWU)            // uint32 per tile
#define SMEM_BYTES (2 * 2 * TILEU * 4)  // 2 stages x (A,B) = 73728 B

__global__ __launch_bounds__(256, 2) void gates_gemm(int npeds) {
  extern __shared__ __align__(16) uint32_t smem[];
  // layout: [stage][A|B][128][ROWU]
  uint32_t* As[2] = { smem,             smem + 2 * TILEU };
  uint32_t* Bs[2] = { smem + TILEU,     smem + 3 * TILEU };

  const int bm = blockIdx.y * 128;
  const int bn = blockIdx.x * 128;
  const int t = threadIdx.x;
  const int warp = t >> 5;
  const int lane = t & 31;
  const int wm = (warp >> 2) * 64;
  const int wn = (warp & 3) * 32;
  const int gr = lane >> 2;   // 0..7
  const int lc = lane & 3;    // 0..3

  float acc[4][4][4];
#pragma unroll
  for (int i = 0; i < 4; ++i)
#pragma unroll
    for (int j = 0; j < 4; ++j)
#pragma unroll
      for (int q = 0; q < 4; ++q) acc[i][j][q] = 0.f;

  const int lrow = t >> 1;        // 0..127
  const int cb = (t & 1) * 4;     // chunk base (8 chunks of 16B per 128B row)

  auto load_tile = [&](int kt, int buf) {
    const __nv_bfloat16* srcA;
    int ldk, koff;
    if (kt == 0) { srcA = g_x; ldk = E; koff = 0; }
    else         { srcA = g_h; ldk = H; koff = (kt - 1) * 64; }
    const __nv_bfloat16* gA0 = srcA + (size_t)(bm + lrow) * ldk + koff;
    const __nv_bfloat16* gB0 = g_Wn + (size_t)(bn + lrow) * KTOT + kt * 64;
    uint32_t dA0 = (uint32_t)__cvta_generic_to_shared(&As[buf][lrow * ROWU]);
    uint32_t dB0 = (uint32_t)__cvta_generic_to_shared(&Bs[buf][lrow * ROWU]);
#pragma unroll
    for (int i = 0; i < 4; ++i) {
      const int ck = cb + i;
      asm volatile("cp.async.cg.shared.global [%0], [%1], 16;\n"
                   :: "r"(dA0 + ck * 16), "l"(gA0 + ck * 8));
      asm volatile("cp.async.cg.shared.global [%0], [%1], 16;\n"
                   :: "r"(dB0 + ck * 16), "l"(gB0 + ck * 8));
    }
    asm volatile("cp.async.commit_group;\n");
  };

  load_tile(0, 0);

  for (int kt = 0; kt < NT; ++kt) {
    asm volatile("cp.async.wait_group 0;\n");
    __syncthreads();
    if (kt + 1 < NT) load_tile(kt + 1, (kt + 1) & 1);
    const int buf = kt & 1;
    const uint32_t* Ab = As[buf];
    const uint32_t* Bb = Bs[buf];

#pragma unroll
    for (int ks = 0; ks < 4; ++ks) {
      const int kb = ks * 8;
      uint32_t a[4][4], b[4][2];
#pragma unroll
      for (int mt = 0; mt < 4; ++mt) {
        const int ar = wm + mt * 16 + gr;
        a[mt][0] = Ab[ar * ROWU + kb + lc];
        a[mt][1] = Ab[(ar + 8) * ROWU + kb + lc];
        a[mt][2] = Ab[ar * ROWU + kb + lc + 4];
        a[mt][3] = Ab[(ar + 8) * ROWU + kb + lc + 4];
      }
#pragma unroll
      for (int nt = 0; nt < 4; ++nt) {
        const int br = wn + nt * 8 + gr;
        b[nt][0] = Bb[br * ROWU + kb + lc];
        b[nt][1] = Bb[br * ROWU + kb + lc + 4];
      }
#pragma unroll
      for (int mt = 0; mt < 4; ++mt)
#pragma unroll
        for (int nt = 0; nt < 4; ++nt) {
          asm volatile(
            "mma.sync.aligned.m16n8k16.row.col.f32.bf16.bf16.f32 "
            "{%0,%1,%2,%3}, {%4,%5,%6,%7}, {%8,%9}, {%0,%1,%2,%3};"
            : "+f"(acc[mt][nt][0]), "+f"(acc[mt][nt][1]),
              "+f"(acc[mt][nt][2]), "+f"(acc[mt][nt][3])
            : "r"(a[mt][0]), "r"(a[mt][1]), "r"(a[mt][2]), "r"(a[mt][3]),
              "r"(b[nt][0]), "r"(b[nt][1]));
        }
    }
  }

  // ---- epilogue: write fp32 gates ----
#pragma unroll
  for (int mt = 0; mt < 4; ++mt) {
    const int row = bm + wm + mt * 16 + gr;
#pragma unroll
    for (int nt = 0; nt < 4; ++nt) {
      const int col = bn + wn + nt * 8 + lc * 2;
      *(float2*)(g_gates + (size_t)row * G4 + col) =
          make_float2(acc[mt][nt][0], acc[mt][nt][1]);
      *(float2*)(g_gates + (size_t)(row + 8) * G4 + col) =
          make_float2(acc[mt][nt][2], acc[mt][nt][3]);
    }
  }
}

// ---------------------------------------------------------------------------
// Fused per-step tail: LSTM elementwise + LN2 + pos projection (rel out) +
// embed(rel) -> next x. One warp per ped; fast MUFU-based activations.
// ---------------------------------------------------------------------------
__global__ __launch_bounds__(256) void lstm_fused(
    const float* __restrict__ ln2_g, const float* __restrict__ ln2_b,
    const float* __restrict__ pos_W, const float* __restrict__ pos_b,
    const float* __restrict__ emb_W, const float* __restrict__ emb_b,
    const float* __restrict__ ln1_g, const float* __restrict__ ln1_b,
    float* __restrict__ rel_out, int npeds) {
  const int warp = threadIdx.x >> 5;
  const int lane = threadIdx.x & 31;
  const int ped = blockIdx.x * 8 + warp;
  if (ped >= npeds) return;

  const float* gp = g_gates + (size_t)ped * G4;
  float* cp = g_c + (size_t)ped * H;
  __nv_bfloat16* hp = g_h + (size_t)ped * H;

  float hn[8];
  float s = 0.f, ss = 0.f;
#pragma unroll
  for (int j = 0; j < 8; ++j) {
    const int ch = lane + j * 32;
    const float ig = gp[ch]           + g_bias[ch];
    const float fg = gp[256 + ch]     + g_bias[256 + ch];
    const float gg = gp[512 + ch]     + g_bias[512 + ch];
    const float og = gp[768 + ch]     + g_bias[768 + ch];
    const float cv = cp[ch];
    const float cn = sigm(fg) * cv + sigm(ig) * tanh_fast(gg);
    const float hv = sigm(og) * tanh_fast(cn);
    cp[ch] = cn;
    hp[ch] = __float2bfloat16(hv);
    hn[j] = hv;
    s += hv;
    ss += hv * hv;
  }
#pragma unroll
  for (int o = 16; o > 0; o >>= 1) {
    s += __shfl_xor_sync(0xffffffffu, s, o);
    ss += __shfl_xor_sync(0xffffffffu, ss, o);
  }
  const float mu = s * (1.f / 256.f);
  const float var = ss * (1.f / 256.f) - mu * mu;
  const float rstd = rsqrtf(var + 1e-5f);

  float d0 = 0.f, d1 = 0.f;
#pragma unroll
  for (int j = 0; j < 8; ++j) {
    const int ch = lane + j * 32;
    const float nh = (hn[j] - mu) * rstd * ln2_g[ch] + ln2_b[ch];
    d0 += nh * pos_W[ch];
    d1 += nh * pos_W[256 + ch];
  }
#pragma unroll
  for (int o = 16; o > 0; o >>= 1) {
    d0 += __shfl_xor_sync(0xffffffffu, d0, o);
    d1 += __shfl_xor_sync(0xffffffffu, d1, o);
  }
  const float r0 = sigm(d0 + pos_b[0]);
  const float r1 = sigm(d1 + pos_b[1]);
  if (lane == 0) {
    rel_out[(size_t)ped * 2 + 0] = r0;
    rel_out[(size_t)ped * 2 + 1] = r1;
  }

  // embed(rel) -> next x  (LN over 2 elems)
  const float d = 0.5f * (r0 - r1);
  const float inv = rsqrtf(d * d + 1e-5f);
  const float na =  d * inv * ln1_g[0] + ln1_b[0];
  const float nb = -d * inv * ln1_g[1] + ln1_b[1];
  __nv_bfloat16* xp = g_x + (size_t)ped * E;
#pragma unroll
  for (int q = 0; q < 2; ++q) {
    const int j = lane * 2 + q;
    const float y = na * emb_W[j * 2 + 0] + nb * emb_W[j * 2 + 1] + emb_b[j];
    xp[j] = __float2bfloat16((y > 0.f) ? y : 0.01f * y);
  }
}

// ---------------------------------------------------------------------------
extern "C" void kernel_launch(void* const* d_in, const int* in_sizes, int n_in,
                              void* d_out, int out_size) {
  const float* last_pos_rel = (const float*)d_in[1];
  const float* h0   = (const float*)d_in[2];
  const float* c0   = (const float*)d_in[3];
  const float* W_ih = (const float*)d_in[4];
  const float* W_hh = (const float*)d_in[5];
  const float* b_ih = (const float*)d_in[6];
  const float* b_hh = (const float*)d_in[7];
  const float* emb_W = (const float*)d_in[8];
  const float* emb_b = (const float*)d_in[9];
  const float* ln1_g = (const float*)d_in[10];
  const float* ln1_b = (const float*)d_in[11];
  const float* pos_W = (const float*)d_in[12];
  const float* pos_b = (const float*)d_in[13];
  const float* ln2_g = (const float*)d_in[14];
  const float* ln2_b = (const float*)d_in[15];
  float* out = (float*)d_out;

  const int npeds = in_sizes[0] / 2;  // 8192

  static int smem_set = 0;
  if (!smem_set) {
    cudaFuncSetAttribute(gates_gemm, cudaFuncAttributeMaxDynamicSharedMemorySize,
                         SMEM_BYTES);
    smem_set = 1;
  }

  prep_weights<<<(G4 * KTOT + 255) / 256, 256>>>(W_ih, W_hh, b_ih, b_hh);
  init_state<<<(npeds * H + 255) / 256, 256>>>(h0, c0, npeds * H);
  embed_init<<<(npeds * E + 255) / 256, 256>>>(last_pos_rel, ln1_g, ln1_b, emb_W, emb_b, npeds);

  dim3 ggrid(G4 / 128, npeds / 128);
  for (int s = 0; s < SEQ; ++s) {
    gates_gemm<<<ggrid, 256, SMEM_BYTES>>>(npeds);
    lstm_fused<<<npeds / 8, 256>>>(ln2_g, ln2_b, pos_W, pos_b, emb_W, emb_b,
                                   ln1_g, ln1_b, out + (size_t)s * npeds * 2, npeds);
  }
}